// round 15
// baseline (speedup 1.0000x reference)
#include <cuda_runtime.h>
#include <cuda_bf16.h>

// Two kernels. result(row) = sum over 28 chunk-pair tables T_(A,B)[nA][nB]
// (32 bits -> 8 nibbles; all 528 order<=2 terms folded into tables).
// Eval: per block, 4 row tiles (256 rows = 32KB each) + the 28KB table are
// fetched with 5 bulk-TMA copies (cp.async.bulk + mbarrier complete_tx) --
// one instruction each, no per-16B LSU traffic. Tile reads are conflict-free
// LDS.128; nibbles packed via butterfly shuffles; 28 smem lookups per row.

#define NPAIRS 28
#define TABSZ (NPAIRS * 256)            // 7168 floats = 28672 B
#define TILE_ROWS 256
#define TILE_BYTES (TILE_ROWS * 128)    // 32768
#define NTILES 4
#define MBAR_OFF 0                      // 5 mbarriers (8B each)
#define TAB_OFF 128
#define BUF_OFF (TAB_OFF + 28672)       // 28800
#define SMEM_TOTAL (BUF_OFF + NTILES * TILE_BYTES)   // 159872 B

__device__ float g_tab[TABSZ];

__device__ __forceinline__ unsigned smem_addr_u32(const void* p) {
    unsigned a;
    asm("{ .reg .u64 t; cvta.to.shared.u64 t, %1; cvt.u32.u64 %0, t; }"
        : "=r"(a) : "l"(p));
    return a;
}
__device__ __forceinline__ void mbar_init(unsigned addr, unsigned count) {
    asm volatile("mbarrier.init.shared.b64 [%0], %1;"
                 :: "r"(addr), "r"(count) : "memory");
}
__device__ __forceinline__ void mbar_expect_tx(unsigned addr, unsigned bytes) {
    asm volatile("mbarrier.arrive.expect_tx.shared.b64 _, [%0], %1;"
                 :: "r"(addr), "r"(bytes) : "memory");
}
__device__ __forceinline__ void bulk_g2s(unsigned dst, const void* src,
                                         unsigned bytes, unsigned mbar) {
    asm volatile(
        "cp.async.bulk.shared::cluster.global.mbarrier::complete_tx::bytes "
        "[%0], [%1], %2, [%3];"
        :: "r"(dst), "l"(src), "r"(bytes), "r"(mbar) : "memory");
}
__device__ __forceinline__ void mbar_wait(unsigned addr) {
    unsigned done;
    asm volatile(
        "{\n\t.reg .pred p;\n\t"
        "mbarrier.try_wait.parity.acquire.cta.shared::cta.b64 p, [%1], 0;\n\t"
        "selp.b32 %0, 1, 0, p;\n\t}"
        : "=r"(done) : "r"(addr) : "memory");
    while (!done) {
        asm volatile(
            "{\n\t.reg .pred p;\n\t"
            "mbarrier.try_wait.parity.acquire.cta.shared::cta.b64 p, [%1], 0, 0x989680;\n\t"
            "selp.b32 %0, 1, 0, p;\n\t}"
            : "=r"(done) : "r"(addr) : "memory");
    }
}

// variables index for pair (i,j), i<j (itertools.combinations order)
__device__ __forceinline__ int pair_v(int i, int j) {
    return 32 + i * 31 - (i * (i - 1)) / 2 + (j - i - 1);
}

__global__ void KOBE_76948634075865_precompute(const float* __restrict__ vars) {
    extern __shared__ float dummy[];   // same dynamic smem as eval: keeps the
    (void)dummy;                       // SM carveout uniform across the graph
    int p = blockIdx.x, t = threadIdx.x;
    int a = t >> 4, b = t & 15;

    int A = 0, rem = p, cnt = 7;
    while (rem >= cnt) { rem -= cnt; cnt--; A++; }
    int B = A + 1 + rem;

    float sa[4], sb[4];
#pragma unroll
    for (int k = 0; k < 4; k++) {
        sa[k] = 1.0f - 2.0f * (float)((a >> k) & 1);
        sb[k] = 1.0f - 2.0f * (float)((b >> k) & 1);
    }

    float acc = 0.0f;
#pragma unroll
    for (int i2 = 0; i2 < 4; i2++)
#pragma unroll
        for (int j2 = 0; j2 < 4; j2++)
            acc += vars[pair_v(4 * A + i2, 4 * B + j2)] * sa[i2] * sb[j2];

    if (B == 7) {
#pragma unroll
        for (int i2 = 0; i2 < 4; i2++) {
            acc += vars[4 * A + i2] * sa[i2];
#pragma unroll
            for (int j2 = i2 + 1; j2 < 4; j2++)
                acc += vars[pair_v(4 * A + i2, 4 * A + j2)] * sa[i2] * sa[j2];
        }
        if (A == 6) {
#pragma unroll
            for (int i2 = 0; i2 < 4; i2++) {
                acc += vars[28 + i2] * sb[i2];
#pragma unroll
                for (int j2 = i2 + 1; j2 < 4; j2++)
                    acc += vars[pair_v(28 + i2, 28 + j2)] * sb[i2] * sb[j2];
            }
        }
    }

    g_tab[p * 256 + a * 16 + b] = acc;
}

__global__ __launch_bounds__(256) void KOBE_76948634075865_eval(
    const char* __restrict__ bits, float* __restrict__ out, int batch) {
    extern __shared__ char smem[];
    unsigned sbase = smem_addr_u32(smem);
    int tid = threadIdx.x;

    if (tid == 0) {
#pragma unroll
        for (int i = 0; i < 5; i++) mbar_init(sbase + MBAR_OFF + i * 8, 1);
    }
    __syncthreads();

    long long tile0 = (long long)blockIdx.x * NTILES;
    if (tid == 0) {
        mbar_expect_tx(sbase + MBAR_OFF, 28672);
        bulk_g2s(sbase + TAB_OFF, g_tab, 28672, sbase + MBAR_OFF);
#pragma unroll
        for (int i = 0; i < NTILES; i++) {
            long long r0 = (tile0 + i) * TILE_ROWS;
            if (r0 < batch) {
                long long rows = batch - r0;
                unsigned bytes = rows >= TILE_ROWS ? TILE_BYTES
                                                   : (unsigned)(rows * 128);
                mbar_expect_tx(sbase + MBAR_OFF + 8 + i * 8, bytes);
                bulk_g2s(sbase + BUF_OFF + i * TILE_BYTES, bits + r0 * 128,
                         bytes, sbase + MBAR_OFF + 8 + i * 8);
            }
        }
    }

    const float* tab = (const float*)(smem + TAB_OFF);
    int chunkpos = tid & 7;
    int myrow_in_tile = chunkpos * 32 + (tid >> 3);   // row this thread owns

    mbar_wait(sbase + MBAR_OFF);                       // table ready

#pragma unroll
    for (int i = 0; i < NTILES; i++) {
        long long r0 = (tile0 + i) * TILE_ROWS;
        if (r0 >= batch) break;
        mbar_wait(sbase + MBAR_OFF + 8 + i * 8);

        const int4* buf = (const int4*)(smem + BUF_OFF + i * TILE_BYTES);

        // Conflict-free tile read + butterfly nibble pack.
        // k-th LDS.128: thread t reads chunk index k*256+t (addr stride 16B,
        // banks t*4 mod 32 within each 8-lane phase -> no conflicts).
        // Chunks of row (k*32 + t>>3) live in lanes (t & ~7)+0..7; OR over
        // xor-1,2,4 assembles the row word; keep at k == (t&7).
        unsigned packed = 0;
#pragma unroll
        for (int k = 0; k < 8; k++) {
            int4 x = buf[k * 256 + tid];
            int nib = x.x + 2 * x.y + 4 * x.z + 8 * x.w;
            unsigned v = (unsigned)nib << (4 * chunkpos);
            v |= __shfl_xor_sync(0xffffffffu, v, 1);
            v |= __shfl_xor_sync(0xffffffffu, v, 2);
            v |= __shfl_xor_sync(0xffffffffu, v, 4);
            if (k == chunkpos) packed = v;
        }

        int n[8];
#pragma unroll
        for (int k = 0; k < 8; k++) n[k] = (packed >> (4 * k)) & 15;

        float a0 = 0.f, a1 = 0.f, a2 = 0.f, a3 = 0.f;
        int idx = 0;
#pragma unroll
        for (int A = 0; A < 8; A++) {
#pragma unroll
            for (int B = A + 1; B < 8; B++) {
                float v = tab[idx * 256 + n[A] * 16 + n[B]];
                if ((idx & 3) == 0)      a0 += v;
                else if ((idx & 3) == 1) a1 += v;
                else if ((idx & 3) == 2) a2 += v;
                else                     a3 += v;
                idx++;
            }
        }
        long long row = r0 + myrow_in_tile;
        if (row < batch) out[row] = (a0 + a1) + (a2 + a3);
    }
}

extern "C" void kernel_launch(void* const* d_in, const int* in_sizes, int n_in,
                              void* d_out, int out_size) {
    const char* bits = (const char*)d_in[0];    // [BATCH, 32] int32
    const float* vars = (const float*)d_in[1];  // [528] float32
    int batch = in_sizes[0] / 32;
    float* out = (float*)d_out;

    cudaFuncSetAttribute(KOBE_76948634075865_eval,
                         cudaFuncAttributeMaxDynamicSharedMemorySize,
                         SMEM_TOTAL);
    cudaFuncSetAttribute(KOBE_76948634075865_precompute,
                         cudaFuncAttributeMaxDynamicSharedMemorySize,
                         SMEM_TOTAL);

    // same dynamic smem on both launches: carveout never toggles in the graph
    KOBE_76948634075865_precompute<<<NPAIRS, 256, SMEM_TOTAL>>>(vars);

    int G = (batch + NTILES * TILE_ROWS - 1) / (NTILES * TILE_ROWS);   // 128
    KOBE_76948634075865_eval<<<G, 256, SMEM_TOTAL>>>(bits, out, batch);
}

// round 16
// speedup vs baseline: 1.0466x; 1.0466x over previous
#include <cuda_runtime.h>
#include <cuda_bf16.h>

// SINGLE fused kernel. result(row) = sum over 28 chunk-pair tables
// T_(A,B)[nA][nB] (32 bits -> 8 nibbles; all 528 order<=2 terms folded in).
// Per block: factorized table build (~250 instr/thread, overlapped with TMA)
// + 2 row tiles of 512 rows fetched with one bulk-TMA copy each.
// Row reads: linear tile, own row, XOR'd chunk order -> conflict-free LDS.128.

#define NPAIRS 28
#define TILE_ROWS 512
#define TILE_BYTES (TILE_ROWS * 128)    // 65536
#define MBAR_OFF 0                      // 2 mbarriers
#define VS_OFF   128                    // 528 floats
#define W_OFF    2240                   // 1792 floats (W[p][i][b])
#define L_OFF    9408                   // 128 floats (L[A][a])
#define TAB_OFF  9920                   // 7168 floats
#define BUF_OFF  38592
#define SMEM_TOTAL (BUF_OFF + 2 * TILE_BYTES)   // 169664 B

__device__ const int g_cA[NPAIRS] = {0,0,0,0,0,0,0,1,1,1,1,1,1,2,2,2,2,2,
                                     3,3,3,3,4,4,4,5,5,6};
__device__ const int g_cB[NPAIRS] = {1,2,3,4,5,6,7,2,3,4,5,6,7,3,4,5,6,7,
                                     4,5,6,7,5,6,7,6,7,7};

__device__ __forceinline__ unsigned smem_addr_u32(const void* p) {
    unsigned a;
    asm("{ .reg .u64 t; cvta.to.shared.u64 t, %1; cvt.u32.u64 %0, t; }"
        : "=r"(a) : "l"(p));
    return a;
}
__device__ __forceinline__ void mbar_init(unsigned addr, unsigned count) {
    asm volatile("mbarrier.init.shared.b64 [%0], %1;"
                 :: "r"(addr), "r"(count) : "memory");
}
__device__ __forceinline__ void mbar_expect_tx(unsigned addr, unsigned bytes) {
    asm volatile("mbarrier.arrive.expect_tx.shared.b64 _, [%0], %1;"
                 :: "r"(addr), "r"(bytes) : "memory");
}
__device__ __forceinline__ void bulk_g2s(unsigned dst, const void* src,
                                         unsigned bytes, unsigned mbar) {
    asm volatile(
        "cp.async.bulk.shared::cluster.global.mbarrier::complete_tx::bytes "
        "[%0], [%1], %2, [%3];"
        :: "r"(dst), "l"(src), "r"(bytes), "r"(mbar) : "memory");
}
__device__ __forceinline__ void mbar_wait(unsigned addr) {
    unsigned done;
    asm volatile(
        "{\n\t.reg .pred p;\n\t"
        "mbarrier.try_wait.parity.acquire.cta.shared::cta.b64 p, [%1], 0;\n\t"
        "selp.b32 %0, 1, 0, p;\n\t}"
        : "=r"(done) : "r"(addr) : "memory");
    while (!done) {
        asm volatile(
            "{\n\t.reg .pred p;\n\t"
            "mbarrier.try_wait.parity.acquire.cta.shared::cta.b64 p, [%1], 0, 0x989680;\n\t"
            "selp.b32 %0, 1, 0, p;\n\t}"
            : "=r"(done) : "r"(addr) : "memory");
    }
}

// variables index for pair (i,j), i<j (itertools.combinations order)
__device__ __forceinline__ int pair_v(int i, int j) {
    return 32 + i * 31 - (i * (i - 1)) / 2 + (j - i - 1);
}

__global__ __launch_bounds__(512) void KOBE_76948634075865_fused(
    const char* __restrict__ bits, const float* __restrict__ vars,
    float* __restrict__ out, int batch) {
    extern __shared__ char smem[];
    unsigned sbase = smem_addr_u32(smem);
    int tid = threadIdx.x;

    if (tid == 0) {
        mbar_init(sbase + MBAR_OFF, 1);
        mbar_init(sbase + MBAR_OFF + 8, 1);
    }
    __syncthreads();

    long long r0 = (long long)blockIdx.x * (2 * TILE_ROWS);
    long long r1 = r0 + TILE_ROWS;
    if (tid == 0) {
        long long rows0 = batch - r0;
        unsigned b0 = rows0 >= TILE_ROWS ? TILE_BYTES
                                         : (rows0 > 0 ? (unsigned)(rows0 * 128) : 0);
        if (b0) {
            mbar_expect_tx(sbase + MBAR_OFF, b0);
            bulk_g2s(sbase + BUF_OFF, bits + r0 * 128, b0, sbase + MBAR_OFF);
        }
        long long rows1 = batch - r1;
        unsigned b1 = rows1 >= TILE_ROWS ? TILE_BYTES
                                         : (rows1 > 0 ? (unsigned)(rows1 * 128) : 0);
        if (b1) {
            mbar_expect_tx(sbase + MBAR_OFF + 8, b1);
            bulk_g2s(sbase + BUF_OFF + TILE_BYTES, bits + r1 * 128, b1,
                     sbase + MBAR_OFF + 8);
        }
    }

    float* vs  = (float*)(smem + VS_OFF);
    float* W   = (float*)(smem + W_OFF);
    float* Lb  = (float*)(smem + L_OFF);
    float* tab = (float*)(smem + TAB_OFF);

    // stage 0: variables -> smem
    if (tid < 512) vs[tid] = vars[tid];
    if (tid < 16)  vs[512 + tid] = vars[512 + tid];
    __syncthreads();

    // stage 1: W[p][i][b] = sum_j vs[pair(4A+i,4B+j)] * sb_j   (1792 entries)
#pragma unroll
    for (int pass = 0; pass < 4; pass++) {
        int w = pass * 512 + tid;
        if (w < 1792) {
            int p = w >> 6, i = (w >> 4) & 3, b = w & 15;
            int A = g_cA[p], B = g_cB[p];
            float acc = 0.f;
#pragma unroll
            for (int j = 0; j < 4; j++) {
                float sbj = 1.0f - 2.0f * (float)((b >> j) & 1);
                acc = fmaf(vs[pair_v(4 * A + i, 4 * B + j)], sbj, acc);
            }
            W[w] = acc;
        }
    }
    // L[A][a]: linear + intra-chunk terms of chunk A at nibble a (128 entries)
    if (tid < 128) {
        int A = tid >> 4, a = tid & 15;
        float sa[4];
#pragma unroll
        for (int k = 0; k < 4; k++) sa[k] = 1.0f - 2.0f * (float)((a >> k) & 1);
        float acc = 0.f;
#pragma unroll
        for (int i = 0; i < 4; i++) {
            acc = fmaf(vs[4 * A + i], sa[i], acc);
#pragma unroll
            for (int j = i + 1; j < 4; j++)
                acc = fmaf(vs[pair_v(4 * A + i, 4 * A + j)], sa[i] * sa[j], acc);
        }
        Lb[tid] = acc;
    }
    __syncthreads();

    // stage 2: T_p[a][b] = sum_i sa_i * W[p][i][b]  (+ folds)   (7168 entries)
#pragma unroll
    for (int pass = 0; pass < 14; pass++) {
        int e = pass * 512 + tid;
        int p = e >> 8, a = (e >> 4) & 15, b = e & 15;
        int A = g_cA[p], B = g_cB[p];
        float acc = 0.f;
#pragma unroll
        for (int i = 0; i < 4; i++) {
            float sai = 1.0f - 2.0f * (float)((a >> i) & 1);
            acc = fmaf(sai, W[(p * 4 + i) * 16 + b], acc);
        }
        if (B == 7) acc += Lb[A * 16 + a];        // chunk A linear+intra
        if (p == 27) acc += Lb[7 * 16 + b];       // chunk 7 linear+intra
        tab[e] = acc;
    }
    __syncthreads();

    int sw = tid & 7;

    // tile 0
    mbar_wait(sbase + MBAR_OFF);
    {
        const int4* rp = (const int4*)(smem + BUF_OFF) + tid * 8;
        int n[8];
#pragma unroll
        for (int k = 0; k < 8; k++) {
            int idx = k ^ sw;                 // conflict-free chunk order
            int4 x = rp[idx];
            n[idx] = x.x + 2 * x.y + 4 * x.z + 8 * x.w;
        }
        float a0 = 0.f, a1 = 0.f, a2 = 0.f, a3 = 0.f;
        int p = 0;
#pragma unroll
        for (int A = 0; A < 8; A++)
#pragma unroll
            for (int B = A + 1; B < 8; B++) {
                float v = tab[p * 256 + n[A] * 16 + n[B]];
                if ((p & 3) == 0)      a0 += v;
                else if ((p & 3) == 1) a1 += v;
                else if ((p & 3) == 2) a2 += v;
                else                   a3 += v;
                p++;
            }
        long long row = r0 + tid;
        if (row < batch) out[row] = (a0 + a1) + (a2 + a3);
    }

    // tile 1
    mbar_wait(sbase + MBAR_OFF + 8);
    {
        const int4* rp = (const int4*)(smem + BUF_OFF + TILE_BYTES) + tid * 8;
        int n[8];
#pragma unroll
        for (int k = 0; k < 8; k++) {
            int idx = k ^ sw;
            int4 x = rp[idx];
            n[idx] = x.x + 2 * x.y + 4 * x.z + 8 * x.w;
        }
        float a0 = 0.f, a1 = 0.f, a2 = 0.f, a3 = 0.f;
        int p = 0;
#pragma unroll
        for (int A = 0; A < 8; A++)
#pragma unroll
            for (int B = A + 1; B < 8; B++) {
                float v = tab[p * 256 + n[A] * 16 + n[B]];
                if ((p & 3) == 0)      a0 += v;
                else if ((p & 3) == 1) a1 += v;
                else if ((p & 3) == 2) a2 += v;
                else                   a3 += v;
                p++;
            }
        long long row = r1 + tid;
        if (row < batch) out[row] = (a0 + a1) + (a2 + a3);
    }
}

extern "C" void kernel_launch(void* const* d_in, const int* in_sizes, int n_in,
                              void* d_out, int out_size) {
    const char* bits = (const char*)d_in[0];    // [BATCH, 32] int32
    const float* vars = (const float*)d_in[1];  // [528] float32
    int batch = in_sizes[0] / 32;
    float* out = (float*)d_out;

    cudaFuncSetAttribute(KOBE_76948634075865_fused,
                         cudaFuncAttributeMaxDynamicSharedMemorySize,
                         SMEM_TOTAL);

    int G = (batch + 2 * TILE_ROWS - 1) / (2 * TILE_ROWS);   // 128
    KOBE_76948634075865_fused<<<G, 512, SMEM_TOTAL>>>(bits, vars, out, batch);
}